// round 14
// baseline (speedup 1.0000x reference)
#include <cuda_runtime.h>
#include <cuda_bf16.h>
#include <cstdint>

#define BCNT 16
#define QLEN 4096
#define KLEN 4096
#define DIM  256
#define NQROWS (BCNT*QLEN)
#define NKROWS (BCNT*KLEN)

// ---------------- scratch ----------------
__device__ __nv_bfloat16 g_qx_hi[NQROWS*DIM];
__device__ __nv_bfloat16 g_qx_lo[NQROWS*DIM];
__device__ __nv_bfloat16 g_kx_hi[NKROWS*DIM];
__device__ __nv_bfloat16 g_kx_lo[NKROWS*DIM];
__device__ __nv_bfloat16 g_v_hi [NKROWS*DIM];
__device__ __nv_bfloat16 g_v_lo [NKROWS*DIM];
__device__ __nv_bfloat16 g_pj_hi[DIM*DIM];
__device__ __nv_bfloat16 g_pj_lo[DIM*DIM];
__device__ __nv_bfloat16 g_qp_hi[NQROWS*DIM];
__device__ __nv_bfloat16 g_qp_lo[NQROWS*DIM];
__device__ __nv_bfloat16 g_kp_hi[NKROWS*DIM];
__device__ __nv_bfloat16 g_kp_lo[NKROWS*DIM];
__device__ float g_nq[NQROWS];
__device__ float g_nk[NKROWS];
__device__ float g_b1v[BCNT*DIM*DIM];
__device__ __nv_bfloat16 g_b1h[BCNT*DIM*DIM];
__device__ __nv_bfloat16 g_b1l[BCNT*DIM*DIM];
__device__ float g_b1s[BCNT*DIM];

// ---------------- helpers ----------------
static __device__ __forceinline__ uint32_t smem_u32(const void* p){
  uint32_t a;
  asm("{ .reg .u64 t; cvta.to.shared.u64 t, %1; cvt.u32.u64 %0, t; }" : "=r"(a) : "l"(p));
  return a;
}
static __device__ __forceinline__ void cp16(uint32_t dst, const void* src){
  asm volatile("cp.async.cg.shared.global [%0], [%1], 16;" :: "r"(dst), "l"(src) : "memory");
}
static __device__ __forceinline__ void cp16p(uint32_t dst, const void* src, int sz){
  asm volatile("cp.async.cg.shared.global [%0], [%1], 16, %2;" :: "r"(dst), "l"(src), "r"(sz) : "memory");
}
static __device__ __forceinline__ void cp_commit(){ asm volatile("cp.async.commit_group;" ::: "memory"); }
template<int N> static __device__ __forceinline__ void cp_wait(){
  asm volatile("cp.async.wait_group %0;" :: "n"(N) : "memory");
}
static __device__ __forceinline__ void ldsm4(uint32_t* r, uint32_t a){
  asm volatile("ldmatrix.sync.aligned.m8n8.x4.shared.b16 {%0,%1,%2,%3}, [%4];"
    : "=r"(r[0]),"=r"(r[1]),"=r"(r[2]),"=r"(r[3]) : "r"(a));
}
static __device__ __forceinline__ void ldsm4t(uint32_t* r, uint32_t a){
  asm volatile("ldmatrix.sync.aligned.m8n8.x4.trans.shared.b16 {%0,%1,%2,%3}, [%4];"
    : "=r"(r[0]),"=r"(r[1]),"=r"(r[2]),"=r"(r[3]) : "r"(a));
}
static __device__ __forceinline__ void mma_bf16(float* c, const uint32_t* a, const uint32_t* b){
  asm volatile("mma.sync.aligned.m16n8k16.row.col.f32.bf16.bf16.f32 "
    "{%0,%1,%2,%3}, {%4,%5,%6,%7}, {%8,%9}, {%0,%1,%2,%3};"
    : "+f"(c[0]),"+f"(c[1]),"+f"(c[2]),"+f"(c[3])
    : "r"(a[0]),"r"(a[1]),"r"(a[2]),"r"(a[3]), "r"(b[0]),"r"(b[1]));
}
static __device__ __forceinline__ float fast_exp(float x){
  float t = fmaxf(x * 1.4426950408889634f, -125.0f);
  float j = t + 12582912.0f;
  int   ji = __float_as_int(j);
  float f  = t - (j - 12582912.0f);
  float p = 1.33333694e-3f;
  p = fmaf(p, f, 9.61812910e-3f);
  p = fmaf(p, f, 5.55041087e-2f);
  p = fmaf(p, f, 2.40226507e-1f);
  p = fmaf(p, f, 6.93147181e-1f);
  p = fmaf(p, f, 1.0f);
  return __int_as_float(__float_as_int(p) + (ji << 23));
}
static __device__ __forceinline__ void split2(float a, float b, uint32_t& hp, uint32_t& lp){
  __nv_bfloat16 ha = __float2bfloat16(a), hb = __float2bfloat16(b);
  __nv_bfloat16 la = __float2bfloat16(a - __bfloat162float(ha));
  __nv_bfloat16 lb = __float2bfloat16(b - __bfloat162float(hb));
  hp = (uint32_t)__bfloat16_as_ushort(ha) | ((uint32_t)__bfloat16_as_ushort(hb)<<16);
  lp = (uint32_t)__bfloat16_as_ushort(la) | ((uint32_t)__bfloat16_as_ushort(lb)<<16);
}

// ---------------- prep: one launch, y selects q / k / v --------------------------
__global__ void prep_all(const float* __restrict__ qs, const float* __restrict__ ks,
                         const float* __restrict__ vs){
  const int job = blockIdx.y;
  if (job == 2){
    int i = blockIdx.x * blockDim.x + threadIdx.x;
    float4 a = ((const float4*)vs)[i*2], b = ((const float4*)vs)[i*2+1];
    uint32_t h0,l0,h1,l1,h2,l2,h3,l3;
    split2(a.x,a.y,h0,l0); split2(a.z,a.w,h1,l1);
    split2(b.x,b.y,h2,l2); split2(b.z,b.w,h3,l3);
    *(uint4*)&g_v_hi[(size_t)i*8] = make_uint4(h0,h1,h2,h3);
    *(uint4*)&g_v_lo[(size_t)i*8] = make_uint4(l0,l1,l2,l3);
    return;
  }
  const float* X = job ? ks : qs;
  int warp = (blockIdx.x * blockDim.x + threadIdx.x) >> 5;
  int lane = threadIdx.x & 31;
  const float4* row = (const float4*)(X + (size_t)warp * DIM);
  float4 a = row[lane*2], b = row[lane*2+1];
  float s = a.x*a.x+a.y*a.y+a.z*a.z+a.w*a.w + b.x*b.x+b.y*b.y+b.z*b.z+b.w*b.w;
  #pragma unroll
  for (int o = 16; o; o >>= 1) s += __shfl_xor_sync(0xFFFFFFFFu, s, o);
  uint32_t h0,l0,h1,l1,h2,l2,h3,l3;
  split2(a.x,a.y,h0,l0); split2(a.z,a.w,h1,l1);
  split2(b.x,b.y,h2,l2); split2(b.z,b.w,h3,l3);
  uint4 H = make_uint4(h0,h1,h2,h3), L = make_uint4(l0,l1,l2,l3);
  size_t off = (size_t)warp*DIM + lane*8;
  if (job){
    *(uint4*)&g_kx_hi[off] = H; *(uint4*)&g_kx_lo[off] = L;
    if (lane == 0) g_nk[warp] = -0.03125f*s - 2.7725887222397811f;
  } else {
    *(uint4*)&g_qx_hi[off] = H; *(uint4*)&g_qx_lo[off] = L;
    if (lane == 0) g_nq[warp] = -0.03125f*s - 2.7725887222397811f;
  }
}
__global__ void prep_pj_zero(const float* __restrict__ proj){
  int i = blockIdx.x * blockDim.x + threadIdx.x;
  if (i < DIM*DIM/8){
    float4 a = ((const float4*)proj)[i*2], b = ((const float4*)proj)[i*2+1];
    uint32_t h0,l0,h1,l1,h2,l2,h3,l3;
    split2(a.x,a.y,h0,l0); split2(a.z,a.w,h1,l1);
    split2(b.x,b.y,h2,l2); split2(b.z,b.w,h3,l3);
    *(uint4*)&g_pj_hi[(size_t)i*8] = make_uint4(h0,h1,h2,h3);
    *(uint4*)&g_pj_lo[(size_t)i*8] = make_uint4(l0,l1,l2,l3);
  }
  for (int j = i; j < BCNT*DIM*DIM; j += gridDim.x*blockDim.x)
    g_b1v[j] = 0.f;
  for (int j = i; j < BCNT*DIM; j += gridDim.x*blockDim.x)
    g_b1s[j] = 0.f;
}

// ---------------- phi: merged q+k, single-sync 2-stage pipeline -----------------
#define PHI_STAGE 40960
__global__ void __launch_bounds__(256) phi_pipe(const int* __restrict__ vlen)
{
  extern __shared__ char sm[];
  const int tid = threadIdx.x, lane = tid & 31, wid = tid >> 5;
  const int wm = wid & 3, wn = wid >> 2;
  const int which = blockIdx.z;
  const int row0 = blockIdx.y * 128, col0 = blockIdx.x * 128;
  const uint32_t sb = smem_u32(sm);
  const __nv_bfloat16* Ah = which ? g_kx_hi : g_qx_hi;
  const __nv_bfloat16* Al = which ? g_kx_lo : g_qx_lo;

  float acc[2][8][4];
  #pragma unroll
  for (int i = 0; i < 2; i++)
    #pragma unroll
    for (int j = 0; j < 8; j++)
      #pragma unroll
      for (int k = 0; k < 4; k++) acc[i][j][k] = 0.f;

  auto load_stage = [&](int s, int k0){
    #pragma unroll
    for (int it = 0; it < 2; it++){
      int i = tid + it*256;
      int r = i >> 2, ch = (i & 3);
      uint32_t d = sb + s*PHI_STAGE + r*80 + ch*16;
      size_t soA = (size_t)(row0+r)*DIM + k0 + ch*8;
      size_t soB = (size_t)(col0+r)*DIM + k0 + ch*8;
      cp16(d,         Ah + soA);
      cp16(d + 10240, Al + soA);
      cp16(d + 20480, g_pj_hi + soB);
      cp16(d + 30720, g_pj_lo + soB);
    }
  };

  const int a_r = (lane&7) + ((lane>>3)&1)*8, a_c16 = (lane>>4)*16;
  const int b_r = (lane&7) + (lane>>4)*8,     b_c16 = ((lane>>3)&1)*16;

  load_stage(0, 0);
  cp_commit();
  #pragma unroll 1
  for (int kt = 0; kt < 8; kt++){
    cp_wait<0>();
    __syncthreads();
    if (kt < 7){ load_stage((kt+1)&1, (kt+1)*32); cp_commit(); }
    const uint32_t base = sb + (kt&1)*PHI_STAGE;
    #pragma unroll
    for (int h = 0; h < 2; h++){
      uint32_t ah[2][4], al[2][4], bh[4][4], bl[4][4];
      #pragma unroll
      for (int mi = 0; mi < 2; mi++){
        uint32_t ad = base + (uint32_t)(wm*32 + mi*16 + a_r)*80 + a_c16 + h*32;
        ldsm4(ah[mi], ad);
        ldsm4(al[mi], ad + 10240);
      }
      #pragma unroll
      for (int ng = 0; ng < 4; ng++){
        uint32_t bd = base + 20480 + (uint32_t)(wn*64 + ng*16 + b_r)*80 + b_c16 + h*32;
        ldsm4(bh[ng], bd);
        ldsm4(bl[ng], bd + 10240);
      }
      #pragma unroll
      for (int mi = 0; mi < 2; mi++)
        #pragma unroll
        for (int ng = 0; ng < 4; ng++){
          mma_bf16(acc[mi][ng*2],   ah[mi], &bh[ng][0]);
          mma_bf16(acc[mi][ng*2+1], ah[mi], &bh[ng][2]);
        }
      #pragma unroll
      for (int mi = 0; mi < 2; mi++)
        #pragma unroll
        for (int ng = 0; ng < 4; ng++){
          mma_bf16(acc[mi][ng*2],   ah[mi], &bl[ng][0]);
          mma_bf16(acc[mi][ng*2+1], ah[mi], &bl[ng][2]);
        }
      #pragma unroll
      for (int mi = 0; mi < 2; mi++)
        #pragma unroll
        for (int ng = 0; ng < 4; ng++){
          mma_bf16(acc[mi][ng*2],   al[mi], &bh[ng][0]);
          mma_bf16(acc[mi][ng*2+1], al[mi], &bh[ng][2]);
        }
    }
  }
  __syncthreads();   // protect smem reuse by epilogue

  // epilogue: exp -> split -> smem stage (pitch 272) -> coalesced STG
  char* sh = sm;
  char* sl = sm + 34816;
  const int l4 = lane >> 2, l2 = (lane & 3) * 2;
  const int b = row0 >> 12;
  const int vl = which ? vlen[b] : 0;
  const float* nrm = which ? g_nk : g_nq;

  #pragma unroll
  for (int nj = 0; nj < 8; nj++){
    int col = wn*64 + nj*8 + l2;
    float cs0 = 0.f, cs1 = 0.f;
    #pragma unroll
    for (int mi = 0; mi < 2; mi++){
      int rl = wm*32 + mi*16 + l4;
      int r0 = row0 + rl;
      float s0 = nrm[r0], s1 = nrm[r0+8];
      float* c = acc[mi][nj];
      float v00 = fast_exp(fmaf(0.25f, c[0], s0));
      float v01 = fast_exp(fmaf(0.25f, c[1], s0));
      float v10 = fast_exp(fmaf(0.25f, c[2], s1));
      float v11 = fast_exp(fmaf(0.25f, c[3], s1));
      uint32_t h, l;
      split2(v00, v01, h, l);
      *(uint32_t*)(sh + rl*272 + col*2) = h;
      *(uint32_t*)(sl + rl*272 + col*2) = l;
      split2(v10, v11, h, l);
      *(uint32_t*)(sh + (rl+8)*272 + col*2) = h;
      *(uint32_t*)(sl + (rl+8)*272 + col*2) = l;
      if (which){
        int k0i = r0 & 4095, k1i = k0i + 8;
        cs0 += (k0i < vl ? v00 : 0.f) + (k1i < vl ? v10 : 0.f);
        cs1 += (k0i < vl ? v01 : 0.f) + (k1i < vl ? v11 : 0.f);
      }
    }
    if (which){
      #pragma unroll
      for (int o = 4; o <= 16; o <<= 1){
        cs0 += __shfl_xor_sync(0xFFFFFFFFu, cs0, o);
        cs1 += __shfl_xor_sync(0xFFFFFFFFu, cs1, o);
      }
      if (lane < 4){
        atomicAdd(&g_b1s[b*DIM + col0 + col], cs0);
        atomicAdd(&g_b1s[b*DIM + col0 + col + 1], cs1);
      }
    }
  }
  __syncthreads();

  __nv_bfloat16* Oh = which ? g_kp_hi : g_qp_hi;
  __nv_bfloat16* Ol = which ? g_kp_lo : g_qp_lo;
  #pragma unroll
  for (int it = 0; it < 8; it++){
    int idx = tid + it*256;
    int r = idx >> 4, ch = idx & 15;
    uint4 vh = *(uint4*)(sh + r*272 + ch*16);
    uint4 vl4 = *(uint4*)(sl + r*272 + ch*16);
    size_t go = (size_t)(row0 + r)*DIM + col0 + ch*8;
    *(uint4*)&Oh[go] = vh;
    *(uint4*)&Ol[go] = vl4;
  }
}

// ---------------- buf1: 3-stage cp.async pipeline (R13, unchanged) ---------------
#define B1_STAGE 34816
__global__ void __launch_bounds__(256) buf1_pipe(const int* __restrict__ vlen)
{
  extern __shared__ char sm[];
  const int b  = blockIdx.y;
  const int m0 = (blockIdx.x >> 1) * 128, c0 = (blockIdx.x & 1) * 128;
  const int kbeg = blockIdx.z * 512;
  const int kend = min(vlen[b], kbeg + 512);
  if (kbeg >= kend) return;
  const int tid = threadIdx.x, lane = tid & 31, wid = tid >> 5;
  const int wm = wid & 3, wn = wid >> 2;
  const uint32_t sb = smem_u32(sm);
  const int nkt = (kend - kbeg + 31) >> 5;

  float acc[2][8][4];
  #pragma unroll
  for (int i = 0; i < 2; i++)
    #pragma unroll
    for (int j = 0; j < 8; j++)
      #pragma unroll
      for (int k = 0; k < 4; k++) acc[i][j][k] = 0.f;

  auto load_stage = [&](int s, int k0){
    #pragma unroll
    for (int it = 0; it < 2; it++){
      int i = tid + it*256;
      int r = i >> 4, ch = (i & 15);
      int gk = k0 + r;
      int sz = (gk < kend) ? 16 : 0;
      int kr = min(gk, kend - 1);
      uint32_t d = sb + s*B1_STAGE + r*272 + ch*16;
      size_t soA = ((size_t)(b*KLEN + kr))*DIM + m0 + ch*8;
      size_t soB = ((size_t)(b*KLEN + kr))*DIM + c0 + ch*8;
      cp16p(d,         g_kp_hi + soA, sz);
      cp16p(d +  8704, g_kp_lo + soA, sz);
      cp16p(d + 17408, g_v_hi  + soB, sz);
      cp16p(d + 26112, g_v_lo  + soB, sz);
    }
  };

  const int at_k = (lane&7) + (lane>>4)*8,      at_m16 = ((lane>>3)&1)*16;
  const int bt_k = (lane&7) + ((lane>>3)&1)*8,  bt_c16 = (lane>>4)*16;

  load_stage(0, kbeg);
  cp_commit();
  if (nkt > 1){ load_stage(1, kbeg + 32); cp_commit(); }

  #pragma unroll 1
  for (int t = 0; t < nkt; t++){
    if (t + 1 < nkt) cp_wait<1>();
    else             cp_wait<0>();
    __syncthreads();
    if (t + 2 < nkt){
      load_stage((t+2) % 3, kbeg + (t+2)*32);
      cp_commit();
    }
    const uint32_t base = sb + (uint32_t)(t % 3)*B1_STAGE;
    #pragma unroll
    for (int h = 0; h < 2; h++){
      uint32_t ah[2][4], al[2][4], bh[4][4], bl[4][4];
      #pragma unroll
      for (int mi = 0; mi < 2; mi++){
        uint32_t ad = base + (uint32_t)(h*16 + at_k)*272 + (uint32_t)(wm*32 + mi*16)*2 + at_m16;
        ldsm4t(ah[mi], ad);
        ldsm4t(al[mi], ad + 8704);
      }
      #pragma unroll
      for (int ng = 0; ng < 4; ng++){
        uint32_t bd = base + 17408 + (uint32_t)(h*16 + bt_k)*272 + (uint32_t)(wn*64 + ng*16)*2 + bt_c16;
        ldsm4t(bh[ng], bd);
        ldsm4t(bl[ng], bd + 8704);
      }
      #pragma unroll
      for (int mi = 0; mi < 2; mi++)
        #pragma unroll
        for (int ng = 0; ng < 4; ng++){
          mma_bf16(acc[mi][ng*2],   ah[mi], &bh[ng][0]);
          mma_bf16(acc[mi][ng*2+1], ah[mi], &bh[ng][2]);
        }
      #pragma unroll
      for (int mi = 0; mi < 2; mi++)
        #pragma unroll
        for (int ng = 0; ng < 4; ng++){
          mma_bf16(acc[mi][ng*2],   ah[mi], &bl[ng][0]);
          mma_bf16(acc[mi][ng*2+1], ah[mi], &bl[ng][2]);
        }
      #pragma unroll
      for (int mi = 0; mi < 2; mi++)
        #pragma unroll
        for (int ng = 0; ng < 4; ng++){
          mma_bf16(acc[mi][ng*2],   al[mi], &bh[ng][0]);
          mma_bf16(acc[mi][ng*2+1], al[mi], &bh[ng][2]);
        }
    }
  }

  const int l4 = lane >> 2, l2 = (lane & 3) * 2;
  #pragma unroll
  for (int mi = 0; mi < 2; mi++){
    int m = m0 + wm*32 + mi*16 + l4;
    #pragma unroll
    for (int nj = 0; nj < 8; nj++){
      int col = c0 + wn*64 + nj*8 + l2;
      float* c = acc[mi][nj];
      atomicAdd(&g_b1v[((size_t)(b*DIM + m))*DIM + col],     c[0]);
      atomicAdd(&g_b1v[((size_t)(b*DIM + m))*DIM + col + 1], c[1]);
      atomicAdd(&g_b1v[((size_t)(b*DIM + m + 8))*DIM + col],     c[2]);
      atomicAdd(&g_b1v[((size_t)(b*DIM + m + 8))*DIM + col + 1], c[3]);
    }
  }
}

// ---------------- b1v fp32 -> bf16 hi/lo ----------------
__global__ void b1split(){
  for (int j = blockIdx.x*blockDim.x + threadIdx.x; j < BCNT*DIM*DIM; j += gridDim.x*blockDim.x){
    float v = g_b1v[j];
    __nv_bfloat16 h = __float2bfloat16(v);
    g_b1h[j] = h;
    g_b1l[j] = __float2bfloat16(v - __bfloat162float(h));
  }
}

// ---------------- ctx: single-sync 2-stage + in-kernel denominator --------------
#define CTX_STAGE 37888
#define CTX_SMEM  (2*CTX_STAGE + 512)
__global__ void __launch_bounds__(256) ctx_pipe(float* __restrict__ out)
{
  extern __shared__ char sm[];
  const int tid = threadIdx.x, lane = tid & 31, wid = tid >> 5;
  const int wm = wid & 3, wn = wid >> 2;
  const int row0 = blockIdx.y * 128, c0 = blockIdx.x * 128;
  const int b = row0 >> 12;
  const uint32_t sb = smem_u32(sm);
  float* sden = (float*)(sm + 2*CTX_STAGE);

  float acc[2][8][4];
  #pragma unroll
  for (int i = 0; i < 2; i++)
    #pragma unroll
    for (int j = 0; j < 8; j++)
      #pragma unroll
      for (int k = 0; k < 4; k++) acc[i][j][k] = 0.f;

  auto load_stage = [&](int s, int k0){
    #pragma unroll
    for (int it = 0; it < 2; it++){
      int i = tid + it*256;
      {
        int r = i >> 2, ch = (i & 3);
        uint32_t d = sb + s*CTX_STAGE + r*80 + ch*16;
        size_t so = (size_t)(row0+r)*DIM + k0 + ch*8;
        cp16(d,         g_qp_hi + so);
        cp16(d + 10240, g_qp_lo + so);
      }
      {
        int r = i >> 4, ch = (i & 15);
        uint32_t d = sb + s*CTX_STAGE + 20480 + r*272 + ch*16;
        size_t so = ((size_t)(b*DIM + k0 + r))*DIM + c0 + ch*8;
        cp16(d,        g_b1h + so);
        cp16(d + 8704, g_b1l + so);
      }
    }
  };

  const int a_r = (lane&7) + ((lane>>3)&1)*8, a_c16 = (lane>>4)*16;
  const int bt_k = (lane&7) + ((lane>>3)&1)*8, bt_c16 = (lane>>4)*16;

  load_stage(0, 0);
  cp_commit();
  if (tid < 128) sden[tid] = 0.f;
  #pragma unroll 1
  for (int kt = 0; kt < 8; kt++){
    cp_wait<0>();
    __syncthreads();
    if (kt < 7){ load_stage((kt+1)&1, (kt+1)*32); cp_commit(); }
    const uint32_t base = sb + (kt&1)*CTX_STAGE;
    const char* stg = sm + (kt&1)*CTX_STAGE;
    {
      int r = tid >> 1, ko = (tid & 1) * 16;
      const char* arow = stg + (uint32_t)r*80 + ko*2;
      const float2* bs2 = (const float2*)(g_b1s + b*DIM + kt*32 + ko);
      float pd = 0.f;
      #pragma unroll
      for (int j = 0; j < 8; j++){
        float2 h2 = __bfloat1622float2(*(const __nv_bfloat162*)(arow + j*4));
        float2 l2 = __bfloat1622float2(*(const __nv_bfloat162*)(arow + 10240 + j*4));
        float2 s2 = bs2[j];
        pd = fmaf(h2.x + l2.x, s2.x, pd);
        pd = fmaf(h2.y + l2.y, s2.y, pd);
      }
      atomicAdd(&sden[r], pd);
    }
    #pragma unroll
    for (int h = 0; h < 2; h++){
      uint32_t ah[2][4], al[2][4], bh[4][4], bl[4][4];
      #pragma unroll
      for (int mi = 0; mi < 2; mi++){
        uint32_t ad = base + (uint32_t)(wm*32 + mi*16 + a_r)*80 + a_c16 + h*32;
        ldsm4(ah[mi], ad);
        ldsm4(al[mi], ad + 10240);
      }
      #pragma unroll
      for (int ng = 0; ng < 4; ng++){
        uint32_t bd = base + 20480 + (uint32_t)(h*16 + bt_k)*272 + (uint32_t)(wn*64 + ng*16)*2 + bt_c16;
        ldsm4t(bh[ng], bd);
        ldsm4t(bl[ng], bd + 8704);
      }
      #pragma unroll
      for (int mi = 0; mi < 2; mi++)
        #pragma unroll
        for (int ng = 0; ng < 4; ng++){
          mma_bf16(acc[mi][ng*2],   ah[mi], &bh[ng][0]);
          mma_bf16(acc[mi][ng*2+1], ah[mi], &bh[ng][2]);
        }
      #pragma unroll
      for (int mi = 0; mi < 2; mi++)
        #pragma unroll
        for (int ng = 0; ng < 4; ng++){
          mma_bf16(acc[mi][ng*2],   ah[mi], &bl[ng][0]);
          mma_bf16(acc[mi][ng*2+1], ah[mi], &bl[ng][2]);
        }
      #pragma unroll
      for (int mi = 0; mi < 2; mi++)
        #pragma unroll
        for (int ng = 0; ng < 4; ng++){
          mma_bf16(acc[mi][ng*2],   al[mi], &bh[ng][0]);
          mma_bf16(acc[mi][ng*2+1], al[mi], &bh[ng][2]);
        }
    }
  }
  __syncthreads();   // sden atomics complete

  const int l4 = lane >> 2, l2 = (lane & 3) * 2;
  #pragma unroll
  for (int mi = 0; mi < 2; mi++){
    int rl = wm*32 + mi*16 + l4;
    int r0 = row0 + rl;
    float i0 = 1.0f / sden[rl];
    float i1 = 1.0f / sden[rl+8];
    #pragma unroll
    for (int nj = 0; nj < 8; nj++){
      int col = c0 + wn*64 + nj*8 + l2;
      float* c = acc[mi][nj];
      *(float2*)(out + (size_t)r0*DIM + col)     = make_float2(c[0]*i0, c[1]*i0);
      *(float2*)(out + (size_t)(r0+8)*DIM + col) = make_float2(c[2]*i1, c[3]*i1);
    }
  }
}

// ---------------- launch ----------------
extern "C" void kernel_launch(void* const* d_in, const int* in_sizes, int n_in,
                              void* d_out, int out_size) {
  (void)in_sizes; (void)n_in; (void)out_size;
  const float* qs   = (const float*)d_in[0];
  const float* ks   = (const float*)d_in[1];
  const float* vs   = (const float*)d_in[2];
  const int*   vlen = (const int*)  d_in[3];
  const float* proj = (const float*)d_in[4];
  float* out = (float*)d_out;

  cudaFuncSetAttribute(phi_pipe,  cudaFuncAttributeMaxDynamicSharedMemorySize, 2*PHI_STAGE);
  cudaFuncSetAttribute(buf1_pipe, cudaFuncAttributeMaxDynamicSharedMemorySize, 3*B1_STAGE);
  cudaFuncSetAttribute(ctx_pipe,  cudaFuncAttributeMaxDynamicSharedMemorySize, CTX_SMEM);

  prep_all<<<dim3(NQROWS/8, 3), 256>>>(qs, ks, vs);
  prep_pj_zero<<<256, 256>>>(proj);

  phi_pipe<<<dim3(2, NQROWS/128, 2), 256, 2*PHI_STAGE>>>(vlen);

  buf1_pipe<<<dim3(4, BCNT, 8), 256, 3*B1_STAGE>>>(vlen);
  b1split<<<1024, 256>>>();

  ctx_pipe<<<dim3(2, NQROWS/128), 256, CTX_SMEM>>>(out);
}

// round 15
// speedup vs baseline: 1.2227x; 1.2227x over previous
#include <cuda_runtime.h>
#include <cuda_bf16.h>
#include <cstdint>

#define BCNT 16
#define QLEN 4096
#define KLEN 4096
#define DIM  256
#define NQROWS (BCNT*QLEN)
#define NKROWS (BCNT*KLEN)

// ---------------- scratch ----------------
__device__ __nv_bfloat16 g_qx_hi[NQROWS*DIM];
__device__ __nv_bfloat16 g_qx_lo[NQROWS*DIM];
__device__ __nv_bfloat16 g_kx_hi[NKROWS*DIM];
__device__ __nv_bfloat16 g_kx_lo[NKROWS*DIM];
__device__ __nv_bfloat16 g_v_hi [NKROWS*DIM];
__device__ __nv_bfloat16 g_v_lo [NKROWS*DIM];
__device__ __nv_bfloat16 g_pj_hi[DIM*DIM];
__device__ __nv_bfloat16 g_pj_lo[DIM*DIM];
__device__ __nv_bfloat16 g_qp_hi[NQROWS*DIM];
__device__ __nv_bfloat16 g_qp_lo[NQROWS*DIM];
__device__ __nv_bfloat16 g_kp_hi[NKROWS*DIM];
__device__ __nv_bfloat16 g_kp_lo[NKROWS*DIM];
__device__ float g_nq[NQROWS];
__device__ float g_nk[NKROWS];
__device__ float g_b1v[BCNT*DIM*DIM];
__device__ __nv_bfloat16 g_b1h[BCNT*DIM*DIM];
__device__ __nv_bfloat16 g_b1l[BCNT*DIM*DIM];
__device__ float g_b1s[BCNT*DIM];

// ---------------- helpers ----------------
static __device__ __forceinline__ uint32_t smem_u32(const void* p){
  uint32_t a;
  asm("{ .reg .u64 t; cvta.to.shared.u64 t, %1; cvt.u32.u64 %0, t; }" : "=r"(a) : "l"(p));
  return a;
}
static __device__ __forceinline__ void cp16(uint32_t dst, const void* src){
  asm volatile("cp.async.cg.shared.global [%0], [%1], 16;" :: "r"(dst), "l"(src) : "memory");
}
static __device__ __forceinline__ void cp16p(uint32_t dst, const void* src, int sz){
  asm volatile("cp.async.cg.shared.global [%0], [%1], 16, %2;" :: "r"(dst), "l"(src), "r"(sz) : "memory");
}
static __device__ __forceinline__ void cp_commit(){ asm volatile("cp.async.commit_group;" ::: "memory"); }
template<int N> static __device__ __forceinline__ void cp_wait(){
  asm volatile("cp.async.wait_group %0;" :: "n"(N) : "memory");
}
static __device__ __forceinline__ void ldsm4(uint32_t* r, uint32_t a){
  asm volatile("ldmatrix.sync.aligned.m8n8.x4.shared.b16 {%0,%1,%2,%3}, [%4];"
    : "=r"(r[0]),"=r"(r[1]),"=r"(r[2]),"=r"(r[3]) : "r"(a));
}
static __device__ __forceinline__ void ldsm4t(uint32_t* r, uint32_t a){
  asm volatile("ldmatrix.sync.aligned.m8n8.x4.trans.shared.b16 {%0,%1,%2,%3}, [%4];"
    : "=r"(r[0]),"=r"(r[1]),"=r"(r[2]),"=r"(r[3]) : "r"(a));
}
static __device__ __forceinline__ void mma_bf16(float* c, const uint32_t* a, const uint32_t* b){
  asm volatile("mma.sync.aligned.m16n8k16.row.col.f32.bf16.bf16.f32 "
    "{%0,%1,%2,%3}, {%4,%5,%6,%7}, {%8,%9}, {%0,%1,%2,%3};"
    : "+f"(c[0]),"+f"(c[1]),"+f"(c[2]),"+f"(c[3])
    : "r"(a[0]),"r"(a[1]),"r"(a[2]),"r"(a[3]), "r"(b[0]),"r"(b[1]));
}
static __device__ __forceinline__ float fast_exp(float x){
  float t = fmaxf(x * 1.4426950408889634f, -125.0f);
  float j = t + 12582912.0f;
  int   ji = __float_as_int(j);
  float f  = t - (j - 12582912.0f);
  float p = 1.33333694e-3f;
  p = fmaf(p, f, 9.61812910e-3f);
  p = fmaf(p, f, 5.55041087e-2f);
  p = fmaf(p, f, 2.40226507e-1f);
  p = fmaf(p, f, 6.93147181e-1f);
  p = fmaf(p, f, 1.0f);
  return __int_as_float(__float_as_int(p) + (ji << 23));
}
static __device__ __forceinline__ void split2(float a, float b, uint32_t& hp, uint32_t& lp){
  __nv_bfloat16 ha = __float2bfloat16(a), hb = __float2bfloat16(b);
  __nv_bfloat16 la = __float2bfloat16(a - __bfloat162float(ha));
  __nv_bfloat16 lb = __float2bfloat16(b - __bfloat162float(hb));
  hp = (uint32_t)__bfloat16_as_ushort(ha) | ((uint32_t)__bfloat16_as_ushort(hb)<<16);
  lp = (uint32_t)__bfloat16_as_ushort(la) | ((uint32_t)__bfloat16_as_ushort(lb)<<16);
}

// ---------------- prep: one launch, y selects q / k / v --------------------------
__global__ void prep_all(const float* __restrict__ qs, const float* __restrict__ ks,
                         const float* __restrict__ vs){
  const int job = blockIdx.y;
  if (job == 2){
    int i = blockIdx.x * blockDim.x + threadIdx.x;
    float4 a = ((const float4*)vs)[i*2], b = ((const float4*)vs)[i*2+1];
    uint32_t h0,l0,h1,l1,h2,l2,h3,l3;
    split2(a.x,a.y,h0,l0); split2(a.z,a.w,h1,l1);
    split2(b.x,b.y,h2,l2); split2(b.z,b.w,h3,l3);
    *(uint4*)&g_v_hi[(size_t)i*8] = make_uint4(h0,h1,h2,h3);
    *(uint4*)&g_v_lo[(size_t)i*8] = make_uint4(l0,l1,l2,l3);
    return;
  }
  const float* X = job ? ks : qs;
  int warp = (blockIdx.x * blockDim.x + threadIdx.x) >> 5;
  int lane = threadIdx.x & 31;
  const float4* row = (const float4*)(X + (size_t)warp * DIM);
  float4 a = row[lane*2], b = row[lane*2+1];
  float s = a.x*a.x+a.y*a.y+a.z*a.z+a.w*a.w + b.x*b.x+b.y*b.y+b.z*b.z+b.w*b.w;
  #pragma unroll
  for (int o = 16; o; o >>= 1) s += __shfl_xor_sync(0xFFFFFFFFu, s, o);
  uint32_t h0,l0,h1,l1,h2,l2,h3,l3;
  split2(a.x,a.y,h0,l0); split2(a.z,a.w,h1,l1);
  split2(b.x,b.y,h2,l2); split2(b.z,b.w,h3,l3);
  uint4 H = make_uint4(h0,h1,h2,h3), L = make_uint4(l0,l1,l2,l3);
  size_t off = (size_t)warp*DIM + lane*8;
  if (job){
    *(uint4*)&g_kx_hi[off] = H; *(uint4*)&g_kx_lo[off] = L;
    if (lane == 0) g_nk[warp] = -0.03125f*s - 2.7725887222397811f;
  } else {
    *(uint4*)&g_qx_hi[off] = H; *(uint4*)&g_qx_lo[off] = L;
    if (lane == 0) g_nq[warp] = -0.03125f*s - 2.7725887222397811f;
  }
}
__global__ void prep_pj_zero(const float* __restrict__ proj){
  int i = blockIdx.x * blockDim.x + threadIdx.x;
  if (i < DIM*DIM/8){
    float4 a = ((const float4*)proj)[i*2], b = ((const float4*)proj)[i*2+1];
    uint32_t h0,l0,h1,l1,h2,l2,h3,l3;
    split2(a.x,a.y,h0,l0); split2(a.z,a.w,h1,l1);
    split2(b.x,b.y,h2,l2); split2(b.z,b.w,h3,l3);
    *(uint4*)&g_pj_hi[(size_t)i*8] = make_uint4(h0,h1,h2,h3);
    *(uint4*)&g_pj_lo[(size_t)i*8] = make_uint4(l0,l1,l2,l3);
  }
  for (int j = i; j < BCNT*DIM*DIM; j += gridDim.x*blockDim.x)
    g_b1v[j] = 0.f;
  for (int j = i; j < BCNT*DIM; j += gridDim.x*blockDim.x)
    g_b1s[j] = 0.f;
}

// ---------------- phi: merged q+k, R13 two-barrier pipeline, staged epilogue ----
#define PHI_STAGE 40960
__global__ void __launch_bounds__(256) phi_pipe(const int* __restrict__ vlen)
{
  extern __shared__ char sm[];
  const int tid = threadIdx.x, lane = tid & 31, wid = tid >> 5;
  const int wm = wid & 3, wn = wid >> 2;
  const int which = blockIdx.z;
  const int row0 = blockIdx.y * 128, col0 = blockIdx.x * 128;
  const uint32_t sb = smem_u32(sm);
  const __nv_bfloat16* Ah = which ? g_kx_hi : g_qx_hi;
  const __nv_bfloat16* Al = which ? g_kx_lo : g_qx_lo;

  float acc[2][8][4];
  #pragma unroll
  for (int i = 0; i < 2; i++)
    #pragma unroll
    for (int j = 0; j < 8; j++)
      #pragma unroll
      for (int k = 0; k < 4; k++) acc[i][j][k] = 0.f;

  auto load_stage = [&](int s, int k0){
    #pragma unroll
    for (int it = 0; it < 2; it++){
      int i = tid + it*256;
      int r = i >> 2, ch = (i & 3);
      uint32_t d = sb + s*PHI_STAGE + r*80 + ch*16;
      size_t soA = (size_t)(row0+r)*DIM + k0 + ch*8;
      size_t soB = (size_t)(col0+r)*DIM + k0 + ch*8;
      cp16(d,         Ah + soA);
      cp16(d + 10240, Al + soA);
      cp16(d + 20480, g_pj_hi + soB);
      cp16(d + 30720, g_pj_lo + soB);
    }
  };

  const int a_r = (lane&7) + ((lane>>3)&1)*8, a_c16 = (lane>>4)*16;
  const int b_r = (lane&7) + (lane>>4)*8,     b_c16 = ((lane>>3)&1)*16;

  load_stage(0, 0);
  cp_commit();
  #pragma unroll 1
  for (int kt = 0; kt < 8; kt++){
    if (kt < 7){ load_stage((kt+1)&1, (kt+1)*32); cp_commit(); cp_wait<1>(); }
    else cp_wait<0>();
    __syncthreads();
    const uint32_t base = sb + (kt&1)*PHI_STAGE;
    #pragma unroll
    for (int h = 0; h < 2; h++){
      uint32_t ah[2][4], al[2][4], bh[4][4], bl[4][4];
      #pragma unroll
      for (int mi = 0; mi < 2; mi++){
        uint32_t ad = base + (uint32_t)(wm*32 + mi*16 + a_r)*80 + a_c16 + h*32;
        ldsm4(ah[mi], ad);
        ldsm4(al[mi], ad + 10240);
      }
      #pragma unroll
      for (int ng = 0; ng < 4; ng++){
        uint32_t bd = base + 20480 + (uint32_t)(wn*64 + ng*16 + b_r)*80 + b_c16 + h*32;
        ldsm4(bh[ng], bd);
        ldsm4(bl[ng], bd + 10240);
      }
      #pragma unroll
      for (int mi = 0; mi < 2; mi++)
        #pragma unroll
        for (int ng = 0; ng < 4; ng++){
          mma_bf16(acc[mi][ng*2],   ah[mi], &bh[ng][0]);
          mma_bf16(acc[mi][ng*2+1], ah[mi], &bh[ng][2]);
        }
      #pragma unroll
      for (int mi = 0; mi < 2; mi++)
        #pragma unroll
        for (int ng = 0; ng < 4; ng++){
          mma_bf16(acc[mi][ng*2],   ah[mi], &bl[ng][0]);
          mma_bf16(acc[mi][ng*2+1], ah[mi], &bl[ng][2]);
        }
      #pragma unroll
      for (int mi = 0; mi < 2; mi++)
        #pragma unroll
        for (int ng = 0; ng < 4; ng++){
          mma_bf16(acc[mi][ng*2],   al[mi], &bh[ng][0]);
          mma_bf16(acc[mi][ng*2+1], al[mi], &bh[ng][2]);
        }
    }
    __syncthreads();
  }

  // epilogue: exp -> split -> smem stage (pitch 272) -> coalesced STG
  char* sh = sm;
  char* sl = sm + 34816;
  const int l4 = lane >> 2, l2 = (lane & 3) * 2;
  const int b = row0 >> 12;
  const int vl = which ? vlen[b] : 0;
  const float* nrm = which ? g_nk : g_nq;

  #pragma unroll
  for (int nj = 0; nj < 8; nj++){
    int col = wn*64 + nj*8 + l2;
    float cs0 = 0.f, cs1 = 0.f;
    #pragma unroll
    for (int mi = 0; mi < 2; mi++){
      int rl = wm*32 + mi*16 + l4;
      int r0 = row0 + rl;
      float s0 = nrm[r0], s1 = nrm[r0+8];
      float* c = acc[mi][nj];
      float v00 = fast_exp(fmaf(0.25f, c[0], s0));
      float v01 = fast_exp(fmaf(0.25f, c[1], s0));
      float v10 = fast_exp(fmaf(0.25f, c[2], s1));
      float v11 = fast_exp(fmaf(0.25f, c[3], s1));
      uint32_t h, l;
      split2(v00, v01, h, l);
      *(uint32_t*)(sh + rl*272 + col*2) = h;
      *(uint32_t*)(sl + rl*272 + col*2) = l;
      split2(v10, v11, h, l);
      *(uint32_t*)(sh + (rl+8)*272 + col*2) = h;
      *(uint32_t*)(sl + (rl+8)*272 + col*2) = l;
      if (which){
        int k0i = r0 & 4095, k1i = k0i + 8;
        cs0 += (k0i < vl ? v00 : 0.f) + (k1i < vl ? v10 : 0.f);
        cs1 += (k0i < vl ? v01 : 0.f) + (k1i < vl ? v11 : 0.f);
      }
    }
    if (which){
      #pragma unroll
      for (int o = 4; o <= 16; o <<= 1){
        cs0 += __shfl_xor_sync(0xFFFFFFFFu, cs0, o);
        cs1 += __shfl_xor_sync(0xFFFFFFFFu, cs1, o);
      }
      if (lane < 4){
        atomicAdd(&g_b1s[b*DIM + col0 + col], cs0);
        atomicAdd(&g_b1s[b*DIM + col0 + col + 1], cs1);
      }
    }
  }
  __syncthreads();

  __nv_bfloat16* Oh = which ? g_kp_hi : g_qp_hi;
  __nv_bfloat16* Ol = which ? g_kp_lo : g_qp_lo;
  #pragma unroll
  for (int it = 0; it < 8; it++){
    int idx = tid + it*256;
    int r = idx >> 4, ch = idx & 15;
    uint4 vh = *(uint4*)(sh + r*272 + ch*16);
    uint4 vl4 = *(uint4*)(sl + r*272 + ch*16);
    size_t go = (size_t)(row0 + r)*DIM + col0 + ch*8;
    *(uint4*)&Oh[go] = vh;
    *(uint4*)&Ol[go] = vl4;
  }
}

// ---------------- buf1: 3-stage pipeline, capped regs for 2 CTAs/SM --------------
#define B1_STAGE 34816
__global__ void __launch_bounds__(256, 2) buf1_pipe(const int* __restrict__ vlen)
{
  extern __shared__ char sm[];
  const int b  = blockIdx.y;
  const int m0 = (blockIdx.x >> 1) * 128, c0 = (blockIdx.x & 1) * 128;
  const int kbeg = blockIdx.z * 512;
  const int kend = min(vlen[b], kbeg + 512);
  if (kbeg >= kend) return;
  const int tid = threadIdx.x, lane = tid & 31, wid = tid >> 5;
  const int wm = wid & 3, wn = wid >> 2;
  const uint32_t sb = smem_u32(sm);
  const int nkt = (kend - kbeg + 31) >> 5;

  float acc[2][8][4];
  #pragma unroll
  for (int i = 0; i < 2; i++)
    #pragma unroll
    for (int j = 0; j < 8; j++)
      #pragma unroll
      for (int k = 0; k < 4; k++) acc[i][j][k] = 0.f;

  auto load_stage = [&](int s, int k0){
    #pragma unroll
    for (int it = 0; it < 2; it++){
      int i = tid + it*256;
      int r = i >> 4, ch = (i & 15);
      int gk = k0 + r;
      int sz = (gk < kend) ? 16 : 0;
      int kr = min(gk, kend - 1);
      uint32_t d = sb + s*B1_STAGE + r*272 + ch*16;
      size_t soA = ((size_t)(b*KLEN + kr))*DIM + m0 + ch*8;
      size_t soB = ((size_t)(b*KLEN + kr))*DIM + c0 + ch*8;
      cp16p(d,         g_kp_hi + soA, sz);
      cp16p(d +  8704, g_kp_lo + soA, sz);
      cp16p(d + 17408, g_v_hi  + soB, sz);
      cp16p(d + 26112, g_v_lo  + soB, sz);
    }
  };

  const int at_k = (lane&7) + (lane>>4)*8,      at_m16 = ((lane>>3)&1)*16;
  const int bt_k = (lane&7) + ((lane>>3)&1)*8,  bt_c16 = (lane>>4)*16;

  load_stage(0, kbeg);
  cp_commit();
  if (nkt > 1){ load_stage(1, kbeg + 32); cp_commit(); }

  #pragma unroll 1
  for (int t = 0; t < nkt; t++){
    if (t + 1 < nkt) cp_wait<1>();
    else             cp_wait<0>();
    __syncthreads();
    if (t + 2 < nkt){
      load_stage((t+2) % 3, kbeg + (t+2)*32);
      cp_commit();
    }
    const uint32_t base = sb + (uint32_t)(t % 3)*B1_STAGE;
    #pragma unroll
    for (int h = 0; h < 2; h++){
      uint32_t ah[2][4], al[2][4], bh[4][4], bl[4][4];
      #pragma unroll
      for (int mi = 0; mi < 2; mi++){
        uint32_t ad = base + (uint32_t)(h*16 + at_k)*272 + (uint32_t)(wm*32 + mi*16)*2 + at_m16;
        ldsm4t(ah[mi], ad);
        ldsm4t(al[mi], ad + 8704);
      }
      #pragma unroll
      for (int ng = 0; ng < 4; ng++){
        uint32_t bd = base + 17408 + (uint32_t)(h*16 + bt_k)*272 + (uint32_t)(wn*64 + ng*16)*2 + bt_c16;
        ldsm4t(bh[ng], bd);
        ldsm4t(bl[ng], bd + 8704);
      }
      #pragma unroll
      for (int mi = 0; mi < 2; mi++)
        #pragma unroll
        for (int ng = 0; ng < 4; ng++){
          mma_bf16(acc[mi][ng*2],   ah[mi], &bh[ng][0]);
          mma_bf16(acc[mi][ng*2+1], ah[mi], &bh[ng][2]);
        }
      #pragma unroll
      for (int mi = 0; mi < 2; mi++)
        #pragma unroll
        for (int ng = 0; ng < 4; ng++){
          mma_bf16(acc[mi][ng*2],   ah[mi], &bl[ng][0]);
          mma_bf16(acc[mi][ng*2+1], ah[mi], &bl[ng][2]);
        }
      #pragma unroll
      for (int mi = 0; mi < 2; mi++)
        #pragma unroll
        for (int ng = 0; ng < 4; ng++){
          mma_bf16(acc[mi][ng*2],   al[mi], &bh[ng][0]);
          mma_bf16(acc[mi][ng*2+1], al[mi], &bh[ng][2]);
        }
    }
  }

  const int l4 = lane >> 2, l2 = (lane & 3) * 2;
  #pragma unroll
  for (int mi = 0; mi < 2; mi++){
    int m = m0 + wm*32 + mi*16 + l4;
    #pragma unroll
    for (int nj = 0; nj < 8; nj++){
      int col = c0 + wn*64 + nj*8 + l2;
      float* c = acc[mi][nj];
      atomicAdd(&g_b1v[((size_t)(b*DIM + m))*DIM + col],     c[0]);
      atomicAdd(&g_b1v[((size_t)(b*DIM + m))*DIM + col + 1], c[1]);
      atomicAdd(&g_b1v[((size_t)(b*DIM + m + 8))*DIM + col],     c[2]);
      atomicAdd(&g_b1v[((size_t)(b*DIM + m + 8))*DIM + col + 1], c[3]);
    }
  }
}

// ---------------- b1v fp32 -> bf16 hi/lo ----------------
__global__ void b1split(){
  for (int j = blockIdx.x*blockDim.x + threadIdx.x; j < BCNT*DIM*DIM; j += gridDim.x*blockDim.x){
    float v = g_b1v[j];
    __nv_bfloat16 h = __float2bfloat16(v);
    g_b1h[j] = h;
    g_b1l[j] = __float2bfloat16(v - __bfloat162float(h));
  }
}

// ---------------- ctx: R13 two-barrier pipeline + in-kernel denominator --------
#define CTX_STAGE 37888
#define CTX_SMEM  (2*CTX_STAGE + 512)
__global__ void __launch_bounds__(256) ctx_pipe(float* __restrict__ out)
{
  extern __shared__ char sm[];
  const int tid = threadIdx.x, lane = tid & 31, wid = tid >> 5;
  const int wm = wid & 3, wn = wid >> 2;
  const int row0 = blockIdx.y * 128, c0 = blockIdx.x * 128;
  const int b = row0 >> 12;
  const uint32_t sb = smem_u32(sm);
  float* sden = (float*)(sm + 2*CTX_STAGE);

  float acc[2][8][4];
  #pragma unroll
  for (int i = 0; i < 2; i++)
    #pragma unroll
    for (int j = 0; j < 8; j++)
      #pragma unroll
      for (int k = 0; k < 4; k++) acc[i][j][k] = 0.f;

  auto load_stage = [&](int s, int k0){
    #pragma unroll
    for (int it = 0; it < 2; it++){
      int i = tid + it*256;
      {
        int r = i >> 2, ch = (i & 3);
        uint32_t d = sb + s*CTX_STAGE + r*80 + ch*16;
        size_t so = (size_t)(row0+r)*DIM + k0 + ch*8;
        cp16(d,         g_qp_hi + so);
        cp16(d + 10240, g_qp_lo + so);
      }
      {
        int r = i >> 4, ch = (i & 15);
        uint32_t d = sb + s*CTX_STAGE + 20480 + r*272 + ch*16;
        size_t so = ((size_t)(b*DIM + k0 + r))*DIM + c0 + ch*8;
        cp16(d,        g_b1h + so);
        cp16(d + 8704, g_b1l + so);
      }
    }
  };

  const int a_r = (lane&7) + ((lane>>3)&1)*8, a_c16 = (lane>>4)*16;
  const int bt_k = (lane&7) + ((lane>>3)&1)*8, bt_c16 = (lane>>4)*16;

  load_stage(0, 0);
  cp_commit();
  if (tid < 128) sden[tid] = 0.f;
  #pragma unroll 1
  for (int kt = 0; kt < 8; kt++){
    if (kt < 7){ load_stage((kt+1)&1, (kt+1)*32); cp_commit(); cp_wait<1>(); }
    else cp_wait<0>();
    __syncthreads();
    const uint32_t base = sb + (kt&1)*CTX_STAGE;
    const char* stg = sm + (kt&1)*CTX_STAGE;
    {
      int r = tid >> 1, ko = (tid & 1) * 16;
      const char* arow = stg + (uint32_t)r*80 + ko*2;
      const float2* bs2 = (const float2*)(g_b1s + b*DIM + kt*32 + ko);
      float pd = 0.f;
      #pragma unroll
      for (int j = 0; j < 8; j++){
        float2 h2 = __bfloat1622float2(*(const __nv_bfloat162*)(arow + j*4));
        float2 l2 = __bfloat1622float2(*(const __nv_bfloat162*)(arow + 10240 + j*4));
        float2 s2 = bs2[j];
        pd = fmaf(h2.x + l2.x, s2.x, pd);
        pd = fmaf(h2.y + l2.y, s2.y, pd);
      }
      atomicAdd(&sden[r], pd);
    }
    #pragma unroll
    for (int h = 0; h < 2; h++){
      uint32_t ah[2][4], al[2][4], bh[4][4], bl[4][4];
      #pragma unroll
      for (int mi = 0; mi < 2; mi++){
        uint32_t ad = base + (uint32_t)(wm*32 + mi*16 + a_r)*80 + a_c16 + h*32;
        ldsm4(ah[mi], ad);
        ldsm4(al[mi], ad + 10240);
      }
      #pragma unroll
      for (int ng = 0; ng < 4; ng++){
        uint32_t bd = base + 20480 + (uint32_t)(h*16 + bt_k)*272 + (uint32_t)(wn*64 + ng*16)*2 + bt_c16;
        ldsm4t(bh[ng], bd);
        ldsm4t(bl[ng], bd + 8704);
      }
      #pragma unroll
      for (int mi = 0; mi < 2; mi++)
        #pragma unroll
        for (int ng = 0; ng < 4; ng++){
          mma_bf16(acc[mi][ng*2],   ah[mi], &bh[ng][0]);
          mma_bf16(acc[mi][ng*2+1], ah[mi], &bh[ng][2]);
        }
      #pragma unroll
      for (int mi = 0; mi < 2; mi++)
        #pragma unroll
        for (int ng = 0; ng < 4; ng++){
          mma_bf16(acc[mi][ng*2],   ah[mi], &bl[ng][0]);
          mma_bf16(acc[mi][ng*2+1], ah[mi], &bl[ng][2]);
        }
      #pragma unroll
      for (int mi = 0; mi < 2; mi++)
        #pragma unroll
        for (int ng = 0; ng < 4; ng++){
          mma_bf16(acc[mi][ng*2],   al[mi], &bh[ng][0]);
          mma_bf16(acc[mi][ng*2+1], al[mi], &bh[ng][2]);
        }
    }
    __syncthreads();
  }
  __syncthreads();

  const int l4 = lane >> 2, l2 = (lane & 3) * 2;
  #pragma unroll
  for (int mi = 0; mi < 2; mi++){
    int rl = wm*32 + mi*16 + l4;
    int r0 = row0 + rl;
    float i0 = 1.0f / sden[rl];
    float i1 = 1.0f / sden[rl+8];
    #pragma unroll
    for (int nj = 0; nj < 8; nj++){
      int col = c0 + wn*64 + nj*8 + l2;
      float* c = acc[mi][nj];
      *(float2*)(out + (size_t)r0*DIM + col)     = make_float2(c[0]*i0, c[1]*i0);
      *(float2*)(out + (size_t)(r0+8)*DIM + col) = make_float2(c[2]*i1, c[3]*i1);
    }
  }
}

// ---------------- launch ----------------
extern "C" void kernel_launch(void* const* d_in, const int* in_sizes, int n_in,
                              void* d_out, int out_size) {
  (void)in_sizes; (void)n_in; (void)out_size;
  const float* qs   = (const float*)d_in[0];
  const float* ks   = (const float*)d_in[1];
  const float* vs   = (const float*)d_in[2];
  const int*   vlen = (const int*)  d_in[3];
  const float* proj = (const float*)d_in[4];
  float* out = (float*)d_out;

  cudaFuncSetAttribute(phi_pipe,  cudaFuncAttributeMaxDynamicSharedMemorySize, 2*PHI_STAGE);
  cudaFuncSetAttribute(buf1_pipe, cudaFuncAttributeMaxDynamicSharedMemorySize, 3*B1_STAGE);
  cudaFuncSetAttribute(ctx_pipe,  cudaFuncAttributeMaxDynamicSharedMemorySize, CTX_SMEM);

  prep_all<<<dim3(NQROWS/8, 3), 256>>>(qs, ks, vs);
  prep_pj_zero<<<256, 256>>>(proj);

  phi_pipe<<<dim3(2, NQROWS/128, 2), 256, 2*PHI_STAGE>>>(vlen);

  buf1_pipe<<<dim3(4, BCNT, 8), 256, 3*B1_STAGE>>>(vlen);
  b1split<<<1024, 256>>>();

  ctx_pipe<<<dim3(2, NQROWS/128), 256, CTX_SMEM>>>(out);
}